// round 1
// baseline (speedup 1.0000x reference)
#include <cuda_runtime.h>
#include <cuda_bf16.h>

// Problem dims (fixed by reference): z_x (1,256,1024), z_y (1,256,1024)
#define Dd 256
#define Nn 1024
#define Mm 1024
#define TILE_I 8                 // rows per block in K1
#define NB_ROWS (Nn / TILE_I)    // 128 blocks
#define IB 16                    // column-stat row chunks
#define ROWS_PER_CHUNK (Nn / IB) // 64

// Scratch (static __device__ — no runtime allocation)
__device__ float g_S[Nn * Mm];          // 4 MB distance/score matrix
__device__ float g_rowmax[Nn], g_rowsum[Nn];
__device__ float g_pm[IB * Mm], g_ps[IB * Mm];   // partial col online-softmax
__device__ float g_colmax[Mm], g_colsum[Mm];
__device__ float g_pnum[Nn], g_pden[Nn];         // per-block final partials

__device__ __forceinline__ float warpMax(float v) {
    #pragma unroll
    for (int o = 16; o; o >>= 1) v = fmaxf(v, __shfl_xor_sync(0xffffffffu, v, o));
    return v;
}
__device__ __forceinline__ float warpSum(float v) {
    #pragma unroll
    for (int o = 16; o; o >>= 1) v += __shfl_xor_sync(0xffffffffu, v, o);
    return v;
}

// Block-wide reductions for 256 threads (8 warps). `sh` must hold >= 8 floats.
__device__ __forceinline__ float blockMax(float v, float* sh) {
    int lane = threadIdx.x & 31, w = threadIdx.x >> 5;
    v = warpMax(v);
    if (lane == 0) sh[w] = v;
    __syncthreads();
    if (w == 0) {
        float x = (lane < 8) ? sh[lane] : -3.4e38f;
        x = warpMax(x);
        if (lane == 0) sh[0] = x;
    }
    __syncthreads();
    float r = sh[0];
    __syncthreads();
    return r;
}
__device__ __forceinline__ float blockSum(float v, float* sh) {
    int lane = threadIdx.x & 31, w = threadIdx.x >> 5;
    v = warpSum(v);
    if (lane == 0) sh[w] = v;
    __syncthreads();
    if (w == 0) {
        float x = (lane < 8) ? sh[lane] : 0.0f;
        x = warpSum(x);
        if (lane == 0) sh[0] = x;
    }
    __syncthreads();
    float r = sh[0];
    __syncthreads();
    return r;
}

// K1: per 8-row tile — compute S, row max, row expsum.
// Thread t owns columns j = 4t..4t+3 (float4 loads/stores).
__global__ __launch_bounds__(256) void k1_scores_rows(
    const float* __restrict__ zx, const float* __restrict__ zy)
{
    __shared__ float xs[TILE_I][Dd];
    __shared__ float red[8];
    const int t = threadIdx.x;
    const int i0 = blockIdx.x * TILE_I;

    // Load 8 x-rows (transposed gather from z_x: x[i][d] = zx[d*N + i])
    for (int idx = t; idx < TILE_I * Dd; idx += 256) {
        int il = idx >> 8, d = idx & 255;
        xs[il][d] = zx[d * Nn + i0 + il];
    }
    __syncthreads();

    float4 acc[TILE_I];
    #pragma unroll
    for (int il = 0; il < TILE_I; ++il) acc[il] = make_float4(0.f, 0.f, 0.f, 0.f);

    #pragma unroll 2
    for (int d = 0; d < Dd; ++d) {
        float4 y4 = reinterpret_cast<const float4*>(zy + d * Mm)[t];
        #pragma unroll
        for (int il = 0; il < TILE_I; ++il) {
            float xv = xs[il][d];
            acc[il].x += fabsf(xv - y4.x);
            acc[il].y += fabsf(xv - y4.y);
            acc[il].z += fabsf(xv - y4.z);
            acc[il].w += fabsf(xv - y4.w);
        }
    }

    #pragma unroll
    for (int il = 0; il < TILE_I; ++il) {
        float4 s4 = make_float4(-acc[il].x, -acc[il].y, -acc[il].z, -acc[il].w);
        reinterpret_cast<float4*>(g_S + (size_t)(i0 + il) * Mm)[t] = s4;

        float lm = fmaxf(fmaxf(s4.x, s4.y), fmaxf(s4.z, s4.w));
        float m = blockMax(lm, red);
        float ls = __expf(s4.x - m) + __expf(s4.y - m) +
                   __expf(s4.z - m) + __expf(s4.w - m);
        float ssum = blockSum(ls, red);
        if (t == 0) { g_rowmax[i0 + il] = m; g_rowsum[i0 + il] = ssum; }
    }
}

// K2a: partial column max + expsum over 64-row chunks. Coalesced (thread -> column).
__global__ __launch_bounds__(256) void k2a_colpart()
{
    const int t = threadIdx.x;
    const int jb = blockIdx.x & 3;        // which 256-column band
    const int ib = blockIdx.x >> 2;       // which 64-row chunk
    const int j = jb * 256 + t;
    const int ibeg = ib * ROWS_PER_CHUNK;

    float m = -3.4e38f;
    #pragma unroll 8
    for (int i = ibeg; i < ibeg + ROWS_PER_CHUNK; ++i)
        m = fmaxf(m, g_S[(size_t)i * Mm + j]);

    float s = 0.f;
    #pragma unroll 8
    for (int i = ibeg; i < ibeg + ROWS_PER_CHUNK; ++i)
        s += __expf(g_S[(size_t)i * Mm + j] - m);

    g_pm[ib * Mm + j] = m;
    g_ps[ib * Mm + j] = s;
}

// K2b: combine 16 partials per column into colmax/colsum.
__global__ __launch_bounds__(256) void k2b_colcombine()
{
    const int j = blockIdx.x * 256 + threadIdx.x;
    float m = -3.4e38f;
    #pragma unroll
    for (int p = 0; p < IB; ++p) m = fmaxf(m, g_pm[p * Mm + j]);
    float s = 0.f;
    #pragma unroll
    for (int p = 0; p < IB; ++p) s += g_ps[p * Mm + j] * __expf(g_pm[p * Mm + j] - m);
    g_colmax[j] = m;
    g_colsum[j] = s;
}

// K3: per row — u = a + b - a*b; accumulate num += u*s, den += u into per-row partials.
__global__ __launch_bounds__(256) void k3_final_partials()
{
    __shared__ float red[8];
    const int t = threadIdx.x;
    const int i = blockIdx.x;

    const float rm = g_rowmax[i];
    const float rinv = 1.0f / g_rowsum[i];

    float4 s4 = reinterpret_cast<const float4*>(g_S + (size_t)i * Mm)[t];
    float4 cm = reinterpret_cast<const float4*>(g_colmax)[t];
    float4 cs = reinterpret_cast<const float4*>(g_colsum)[t];

    float num = 0.f, den = 0.f;
    {
        float s = s4.x;
        float a = __expf(s - rm) * rinv;
        float b = __expf(s - cm.x) / cs.x;
        float u = a + b - a * b;
        num += u * s; den += u;
    }
    {
        float s = s4.y;
        float a = __expf(s - rm) * rinv;
        float b = __expf(s - cm.y) / cs.y;
        float u = a + b - a * b;
        num += u * s; den += u;
    }
    {
        float s = s4.z;
        float a = __expf(s - rm) * rinv;
        float b = __expf(s - cm.z) / cs.z;
        float u = a + b - a * b;
        num += u * s; den += u;
    }
    {
        float s = s4.w;
        float a = __expf(s - rm) * rinv;
        float b = __expf(s - cm.w) / cs.w;
        float u = a + b - a * b;
        num += u * s; den += u;
    }

    num = blockSum(num, red);
    den = blockSum(den, red);
    if (t == 0) { g_pnum[i] = num; g_pden[i] = den; }
}

// K4: deterministic combine of 1024 row partials -> scalar out.
__global__ __launch_bounds__(256) void k4_combine(float* __restrict__ out)
{
    __shared__ float red[8];
    float num = 0.f, den = 0.f;
    for (int p = threadIdx.x; p < Nn; p += 256) {
        num += g_pnum[p];
        den += g_pden[p];
    }
    num = blockSum(num, red);
    den = blockSum(den, red);
    if (threadIdx.x == 0) out[0] = num / den;
}

extern "C" void kernel_launch(void* const* d_in, const int* in_sizes, int n_in,
                              void* d_out, int out_size)
{
    const float* zx = (const float*)d_in[0];
    const float* zy = (const float*)d_in[1];
    float* out = (float*)d_out;

    k1_scores_rows<<<NB_ROWS, 256>>>(zx, zy);
    k2a_colpart<<<4 * IB, 256>>>();
    k2b_colcombine<<<Mm / 256, 256>>>();
    k3_final_partials<<<Nn, 256>>>();
    k4_combine<<<1, 256>>>(out);
}

// round 2
// speedup vs baseline: 1.2244x; 1.2244x over previous
#include <cuda_runtime.h>
#include <cuda_bf16.h>

#define Dd 256
#define Nn 1024
#define Mm 1024
#define TILE_I 8
#define NB 128            // row blocks in K1 (= Nn / TILE_I)

typedef unsigned long long u64;
typedef unsigned int u32;

// Scratch (static __device__ — no runtime allocation)
__device__ float g_S[Nn * Mm];               // score matrix s = -L1dist (4 MB)
__device__ float g_pm[NB * Mm], g_ps[NB * Mm]; // per-rowgroup column partials
__device__ float g_cm[Mm], g_cinv[Mm];         // column max, 1/colsum
__device__ float g_num[Nn], g_den[Nn];         // per-row final partials

#define FMA2(o, a, b, c) asm("fma.rn.f32x2 %0, %1, %2, %3;" : "=l"(o) : "l"(a), "l"(b), "l"(c))
#define ADD2(o, a, b)    asm("add.rn.f32x2 %0, %1, %2;"     : "=l"(o) : "l"(a), "l"(b))

__device__ __forceinline__ float lo32(u64 v) { return __uint_as_float((u32)v); }
__device__ __forceinline__ float hi32(u64 v) { return __uint_as_float((u32)(v >> 32)); }

__device__ __forceinline__ float warpMax(float v) {
    #pragma unroll
    for (int o = 16; o; o >>= 1) v = fmaxf(v, __shfl_xor_sync(0xffffffffu, v, o));
    return v;
}
__device__ __forceinline__ float warpSum(float v) {
    #pragma unroll
    for (int o = 16; o; o >>= 1) v += __shfl_xor_sync(0xffffffffu, v, o);
    return v;
}

// ===================== K1: scores + per-rowgroup column partials =====================
// Block b owns rows i0..i0+7. Thread t owns columns 4t..4t+3.
// Mainloop: packed f32x2 fma (diff) + 64-bit AND (abs, alu pipe) + packed add.
__global__ __launch_bounds__(256) void k1_scores(
    const float* __restrict__ zx, const float* __restrict__ zy)
{
    __shared__ __align__(16) float2 xs[Dd][TILE_I];   // duplicated (x,x) pairs, 16KB
    const int t = threadIdx.x;
    const int i0 = blockIdx.x * TILE_I;

    for (int idx = t; idx < Dd * TILE_I; idx += 256) {
        int d = idx >> 3, il = idx & 7;
        float v = zx[d * Nn + i0 + il];
        xs[d][il] = make_float2(v, v);
    }
    __syncthreads();

    const u64 NEG1 = 0xBF800000BF800000ULL;   // (-1.0f, -1.0f)
    const u64 ABSM = 0x7FFFFFFF7FFFFFFFULL;   // clear both sign bits

    u64 a0[TILE_I], a1[TILE_I];               // a0: cols 4t,4t+1; a1: cols 4t+2,4t+3
    #pragma unroll
    for (int r = 0; r < TILE_I; ++r) { a0[r] = 0ULL; a1[r] = 0ULL; }

    const ulonglong2* yp = reinterpret_cast<const ulonglong2*>(zy);

    auto body = [&](int d, ulonglong2 y) {
        #pragma unroll
        for (int h = 0; h < TILE_I / 2; ++h) {
            ulonglong2 xp = *reinterpret_cast<const ulonglong2*>(&xs[d][2 * h]);
            u64 d00, d01, d10, d11;
            FMA2(d00, y.x, NEG1, xp.x);       // (x - y) for cols 4t,4t+1, row 2h
            FMA2(d01, y.y, NEG1, xp.x);
            FMA2(d10, y.x, NEG1, xp.y);       // row 2h+1
            FMA2(d11, y.y, NEG1, xp.y);
            d00 &= ABSM; d01 &= ABSM; d10 &= ABSM; d11 &= ABSM;   // |.| via 2x LOP3 each
            ADD2(a0[2 * h],     a0[2 * h],     d00);
            ADD2(a1[2 * h],     a1[2 * h],     d01);
            ADD2(a0[2 * h + 1], a0[2 * h + 1], d10);
            ADD2(a1[2 * h + 1], a1[2 * h + 1], d11);
        }
    };

    ulonglong2 ycur = yp[t];
    #pragma unroll 2
    for (int d = 0; d < Dd - 1; ++d) {
        ulonglong2 ynext = yp[(d + 1) * (Mm / 4) + t];   // prefetch next y row chunk
        body(d, ycur);
        ycur = ynext;
    }
    body(Dd - 1, ycur);

    // Epilogue: store s = -dist, and per-column (over this block's 8 rows) max + expsum.
    float sx[TILE_I], sy[TILE_I], sz[TILE_I], sw[TILE_I];
    #pragma unroll
    for (int r = 0; r < TILE_I; ++r) {
        sx[r] = -lo32(a0[r]); sy[r] = -hi32(a0[r]);
        sz[r] = -lo32(a1[r]); sw[r] = -hi32(a1[r]);
        reinterpret_cast<float4*>(g_S + (size_t)(i0 + r) * Mm)[t] =
            make_float4(sx[r], sy[r], sz[r], sw[r]);
    }
    float mx = sx[0], my = sy[0], mz = sz[0], mw = sw[0];
    #pragma unroll
    for (int r = 1; r < TILE_I; ++r) {
        mx = fmaxf(mx, sx[r]); my = fmaxf(my, sy[r]);
        mz = fmaxf(mz, sz[r]); mw = fmaxf(mw, sw[r]);
    }
    float ex = 0.f, ey = 0.f, ez = 0.f, ew = 0.f;
    #pragma unroll
    for (int r = 0; r < TILE_I; ++r) {
        ex += __expf(sx[r] - mx); ey += __expf(sy[r] - my);
        ez += __expf(sz[r] - mz); ew += __expf(sw[r] - mw);
    }
    reinterpret_cast<float4*>(g_pm + (size_t)blockIdx.x * Mm)[t] = make_float4(mx, my, mz, mw);
    reinterpret_cast<float4*>(g_ps + (size_t)blockIdx.x * Mm)[t] = make_float4(ex, ey, ez, ew);
}

// ===================== K2b: combine 128 column partials =====================
__global__ __launch_bounds__(32) void k2b_colcombine()
{
    const int j = blockIdx.x * 32 + threadIdx.x;
    float m = -3.4e38f;
    #pragma unroll 8
    for (int p = 0; p < NB; ++p) m = fmaxf(m, g_pm[p * Mm + j]);
    float s = 0.f;
    #pragma unroll 8
    for (int p = 0; p < NB; ++p) s += g_ps[p * Mm + j] * __expf(g_pm[p * Mm + j] - m);
    g_cm[j] = m;
    g_cinv[j] = 1.0f / s;
}

// ===================== K3: warp-per-row final partials =====================
__global__ __launch_bounds__(256) void k3_rows()
{
    const int w = threadIdx.x >> 5, lane = threadIdx.x & 31;
    const int i = blockIdx.x * 8 + w;
    const float4* row = reinterpret_cast<const float4*>(g_S + (size_t)i * Mm);

    float4 s[8];
    float m = -3.4e38f;
    #pragma unroll
    for (int q = 0; q < 8; ++q) {
        s[q] = row[q * 32 + lane];
        m = fmaxf(m, fmaxf(fmaxf(s[q].x, s[q].y), fmaxf(s[q].z, s[q].w)));
    }
    m = warpMax(m);

    float4 e[8];
    float rs = 0.f;
    #pragma unroll
    for (int q = 0; q < 8; ++q) {
        e[q].x = __expf(s[q].x - m); e[q].y = __expf(s[q].y - m);
        e[q].z = __expf(s[q].z - m); e[q].w = __expf(s[q].w - m);
        rs += e[q].x + e[q].y + e[q].z + e[q].w;
    }
    rs = warpSum(rs);
    const float rinv = 1.0f / rs;

    float num = 0.f, den = 0.f;
    #pragma unroll
    for (int q = 0; q < 8; ++q) {
        float4 cm = reinterpret_cast<const float4*>(g_cm)[q * 32 + lane];
        float4 ci = reinterpret_cast<const float4*>(g_cinv)[q * 32 + lane];
        {
            float a = e[q].x * rinv, b = __expf(s[q].x - cm.x) * ci.x;
            float u = a + b - a * b; num += u * s[q].x; den += u;
        }
        {
            float a = e[q].y * rinv, b = __expf(s[q].y - cm.y) * ci.y;
            float u = a + b - a * b; num += u * s[q].y; den += u;
        }
        {
            float a = e[q].z * rinv, b = __expf(s[q].z - cm.z) * ci.z;
            float u = a + b - a * b; num += u * s[q].z; den += u;
        }
        {
            float a = e[q].w * rinv, b = __expf(s[q].w - cm.w) * ci.w;
            float u = a + b - a * b; num += u * s[q].w; den += u;
        }
    }
    num = warpSum(num);
    den = warpSum(den);
    if (lane == 0) { g_num[i] = num; g_den[i] = den; }
}

// ===================== K4: deterministic scalar combine =====================
__global__ __launch_bounds__(256) void k4_combine(float* __restrict__ out)
{
    __shared__ float shn[8], shd[8];
    const int t = threadIdx.x, lane = t & 31, w = t >> 5;
    float num = 0.f, den = 0.f;
    for (int p = t; p < Nn; p += 256) { num += g_num[p]; den += g_den[p]; }
    num = warpSum(num); den = warpSum(den);
    if (lane == 0) { shn[w] = num; shd[w] = den; }
    __syncthreads();
    if (w == 0) {
        float n = (lane < 8) ? shn[lane] : 0.f;
        float d = (lane < 8) ? shd[lane] : 0.f;
        n = warpSum(n); d = warpSum(d);
        if (lane == 0) out[0] = n / d;
    }
}

extern "C" void kernel_launch(void* const* d_in, const int* in_sizes, int n_in,
                              void* d_out, int out_size)
{
    const float* zx = (const float*)d_in[0];
    const float* zy = (const float*)d_in[1];
    float* out = (float*)d_out;

    k1_scores<<<NB, 256>>>(zx, zy);
    k2b_colcombine<<<Mm / 32, 32>>>();
    k3_rows<<<Nn / 8, 256>>>();
    k4_combine<<<1, 256>>>(out);
}

// round 3
// speedup vs baseline: 1.5821x; 1.2921x over previous
#include <cuda_runtime.h>
#include <cuda_bf16.h>

#define Dd 256
#define Nn 1024
#define Mm 1024
#define RG 8                  // rows per K1 tile
#define CT 128                // cols per K1 tile
#define NGRP 256              // 4-row column-partial groups (1024/4)

typedef unsigned long long u64;
typedef unsigned int u32;

// Scratch (static __device__ — no runtime allocation)
__device__ float g_S[Nn * Mm];            // score matrix s = -L1dist (4 MB)
__device__ float g_pm[Mm * NGRP];         // col partial max, TRANSPOSED [col][group]
__device__ float g_ps[Mm * NGRP];         // col partial expsum
__device__ float g_cm[Mm], g_cinv[Mm];    // column max, 1/colsum
__device__ float g_num[Nn], g_den[Nn];    // per-row final partials

#define FMA2(o, a, b, c) asm("fma.rn.f32x2 %0, %1, %2, %3;" : "=l"(o) : "l"(a), "l"(b), "l"(c))
#define ADD2(o, a, b)    asm("add.rn.f32x2 %0, %1, %2;"     : "=l"(o) : "l"(a), "l"(b))

__device__ __forceinline__ float lo32(u64 v) { return __uint_as_float((u32)v); }
__device__ __forceinline__ float hi32(u64 v) { return __uint_as_float((u32)(v >> 32)); }

__device__ __forceinline__ float warpMax(float v) {
    #pragma unroll
    for (int o = 16; o; o >>= 1) v = fmaxf(v, __shfl_xor_sync(0xffffffffu, v, o));
    return v;
}
__device__ __forceinline__ float warpSum(float v) {
    #pragma unroll
    for (int o = 16; o; o >>= 1) v += __shfl_xor_sync(0xffffffffu, v, o);
    return v;
}

// ===================== K1: scores + per-4-row-group column partials =====================
// 1024 blocks (128 row-groups x 8 col-tiles), 128 threads.
// Thread t: col pair cp = t&63 (cols j0+2cp, j0+2cp+1), row half rp = t>>6 (rows rp*4..rp*4+3).
__global__ __launch_bounds__(128) void k1_scores(
    const float* __restrict__ zx, const float* __restrict__ zy)
{
    __shared__ __align__(16) float2 xs[Dd][RG];   // duplicated (x,x) pairs, 16KB
    const int t = threadIdx.x;
    const int rg = blockIdx.x >> 3;
    const int ct = blockIdx.x & 7;
    const int i0 = rg * RG, j0 = ct * CT;

    for (int idx = t; idx < Dd * RG; idx += 128) {
        int d = idx >> 3, r = idx & 7;
        float v = zx[d * Nn + i0 + r];
        xs[d][r] = make_float2(v, v);
    }
    __syncthreads();

    const int cp = t & 63;
    const int rp = t >> 6;

    const u64 NEG1 = 0xBF800000BF800000ULL;
    const u64 ABSM = 0x7FFFFFFF7FFFFFFFULL;

    u64 acc0 = 0, acc1 = 0, acc2 = 0, acc3 = 0;

    const u64* yb = reinterpret_cast<const u64*>(zy) + (j0 >> 1) + cp;   // stride 512 per d

    u64 y0 = yb[0];
    u64 y1 = yb[512];

    auto body = [&](int d, u64 yc) {
        ulonglong2 xa = *reinterpret_cast<const ulonglong2*>(&xs[d][rp * 4]);
        ulonglong2 xb = *reinterpret_cast<const ulonglong2*>(&xs[d][rp * 4 + 2]);
        u64 d0, d1, d2, d3;
        FMA2(d0, yc, NEG1, xa.x);
        FMA2(d1, yc, NEG1, xa.y);
        FMA2(d2, yc, NEG1, xb.x);
        FMA2(d3, yc, NEG1, xb.y);
        d0 &= ABSM; d1 &= ABSM; d2 &= ABSM; d3 &= ABSM;
        ADD2(acc0, acc0, d0);
        ADD2(acc1, acc1, d1);
        ADD2(acc2, acc2, d2);
        ADD2(acc3, acc3, d3);
    };

    #pragma unroll 4
    for (int d = 0; d < Dd - 2; ++d) {
        u64 yc = y0; y0 = y1;
        y1 = yb[(size_t)(d + 2) * 512];
        body(d, yc);
    }
    body(Dd - 2, y0);
    body(Dd - 1, y1);

    // Epilogue: store s = -dist (float2, coalesced), and 4-row column partials.
    float sl[4], sh[4];
    sl[0] = -lo32(acc0); sh[0] = -hi32(acc0);
    sl[1] = -lo32(acc1); sh[1] = -hi32(acc1);
    sl[2] = -lo32(acc2); sh[2] = -hi32(acc2);
    sl[3] = -lo32(acc3); sh[3] = -hi32(acc3);

    const int ib = i0 + rp * 4;
    const int j = j0 + 2 * cp;
    #pragma unroll
    for (int r = 0; r < 4; ++r)
        *reinterpret_cast<float2*>(g_S + (size_t)(ib + r) * Mm + j) = make_float2(sl[r], sh[r]);

    float m0 = fmaxf(fmaxf(sl[0], sl[1]), fmaxf(sl[2], sl[3]));
    float m1 = fmaxf(fmaxf(sh[0], sh[1]), fmaxf(sh[2], sh[3]));
    float e0 = __expf(sl[0] - m0) + __expf(sl[1] - m0) + __expf(sl[2] - m0) + __expf(sl[3] - m0);
    float e1 = __expf(sh[0] - m1) + __expf(sh[1] - m1) + __expf(sh[2] - m1) + __expf(sh[3] - m1);

    const int g = rg * 2 + rp;                 // group 0..255
    g_pm[(size_t)j * NGRP + g] = m0;
    g_pm[(size_t)(j + 1) * NGRP + g] = m1;
    g_ps[(size_t)j * NGRP + g] = e0;
    g_ps[(size_t)(j + 1) * NGRP + g] = e1;
}

// ===================== K2: combine 256 column partials (warp per column) =====================
__global__ __launch_bounds__(256) void k2_colcombine()
{
    const int w = threadIdx.x >> 5, lane = threadIdx.x & 31;
    const int j = blockIdx.x * 8 + w;
    const float4* pm = reinterpret_cast<const float4*>(g_pm + (size_t)j * NGRP);
    const float4* ps = reinterpret_cast<const float4*>(g_ps + (size_t)j * NGRP);

    float4 m4a = pm[lane * 2], m4b = pm[lane * 2 + 1];
    float m = fmaxf(fmaxf(fmaxf(m4a.x, m4a.y), fmaxf(m4a.z, m4a.w)),
                    fmaxf(fmaxf(m4b.x, m4b.y), fmaxf(m4b.z, m4b.w)));
    m = warpMax(m);

    float4 s4a = ps[lane * 2], s4b = ps[lane * 2 + 1];
    float s = s4a.x * __expf(m4a.x - m) + s4a.y * __expf(m4a.y - m) +
              s4a.z * __expf(m4a.z - m) + s4a.w * __expf(m4a.w - m) +
              s4b.x * __expf(m4b.x - m) + s4b.y * __expf(m4b.y - m) +
              s4b.z * __expf(m4b.z - m) + s4b.w * __expf(m4b.w - m);
    s = warpSum(s);

    if (lane == 0) { g_cm[j] = m; g_cinv[j] = 1.0f / s; }
}

// ===================== K3: warp-per-row final partials =====================
__global__ __launch_bounds__(128) void k3_rows()
{
    const int w = threadIdx.x >> 5, lane = threadIdx.x & 31;
    const int i = blockIdx.x * 4 + w;
    const float4* row = reinterpret_cast<const float4*>(g_S + (size_t)i * Mm);

    float4 s[8];
    float m = -3.4e38f;
    #pragma unroll
    for (int q = 0; q < 8; ++q) {
        s[q] = row[q * 32 + lane];
        m = fmaxf(m, fmaxf(fmaxf(s[q].x, s[q].y), fmaxf(s[q].z, s[q].w)));
    }
    m = warpMax(m);

    float4 e[8];
    float rs = 0.f;
    #pragma unroll
    for (int q = 0; q < 8; ++q) {
        e[q].x = __expf(s[q].x - m); e[q].y = __expf(s[q].y - m);
        e[q].z = __expf(s[q].z - m); e[q].w = __expf(s[q].w - m);
        rs += e[q].x + e[q].y + e[q].z + e[q].w;
    }
    rs = warpSum(rs);
    const float rinv = 1.0f / rs;

    float num = 0.f, den = 0.f;
    #pragma unroll
    for (int q = 0; q < 8; ++q) {
        float4 cm = reinterpret_cast<const float4*>(g_cm)[q * 32 + lane];
        float4 ci = reinterpret_cast<const float4*>(g_cinv)[q * 32 + lane];
        {
            float a = e[q].x * rinv, b = __expf(s[q].x - cm.x) * ci.x;
            float u = a + b - a * b; num += u * s[q].x; den += u;
        }
        {
            float a = e[q].y * rinv, b = __expf(s[q].y - cm.y) * ci.y;
            float u = a + b - a * b; num += u * s[q].y; den += u;
        }
        {
            float a = e[q].z * rinv, b = __expf(s[q].z - cm.z) * ci.z;
            float u = a + b - a * b; num += u * s[q].z; den += u;
        }
        {
            float a = e[q].w * rinv, b = __expf(s[q].w - cm.w) * ci.w;
            float u = a + b - a * b; num += u * s[q].w; den += u;
        }
    }
    num = warpSum(num);
    den = warpSum(den);
    if (lane == 0) { g_num[i] = num; g_den[i] = den; }
}

// ===================== K4: deterministic scalar combine =====================
__global__ __launch_bounds__(256) void k4_combine(float* __restrict__ out)
{
    __shared__ float shn[8], shd[8];
    const int t = threadIdx.x, lane = t & 31, w = t >> 5;
    float num = 0.f, den = 0.f;
    for (int p = t; p < Nn; p += 256) { num += g_num[p]; den += g_den[p]; }
    num = warpSum(num); den = warpSum(den);
    if (lane == 0) { shn[w] = num; shd[w] = den; }
    __syncthreads();
    if (w == 0) {
        float n = (lane < 8) ? shn[lane] : 0.f;
        float d = (lane < 8) ? shd[lane] : 0.f;
        n = warpSum(n); d = warpSum(d);
        if (lane == 0) out[0] = n / d;
    }
}

extern "C" void kernel_launch(void* const* d_in, const int* in_sizes, int n_in,
                              void* d_out, int out_size)
{
    const float* zx = (const float*)d_in[0];
    const float* zy = (const float*)d_in[1];
    float* out = (float*)d_out;

    k1_scores<<<(Nn / RG) * (Mm / CT), 128>>>(zx, zy);
    k2_colcombine<<<Mm / 8, 256>>>();
    k3_rows<<<Nn / 4, 128>>>();
    k4_combine<<<1, 256>>>(out);
}